// round 8
// baseline (speedup 1.0000x reference)
#include <cuda_runtime.h>
#include <cstdint>

#define BB   64
#define SS   2048
#define HH   256
#define G4   1024
#define MTOT (BB*SS)

// ---------------- scratch (device globals) -----------------------------------
__device__ float    g_xproj[(size_t)MTOT * G4];   // [B*S, 4H] (512 MB)
__device__ float    g_h[2][16 * 1024];            // [parity][bg][k2*8 + b*2 + par]
__device__ unsigned g_flag[128 * 32];             // [(bg*8+hg)*32], 128B apart

// ---------------- f32x2 packed helpers (sm_103a) -----------------------------
__device__ __forceinline__ void ffma2(unsigned long long& d,
                                      unsigned long long a, unsigned long long b) {
    asm("fma.rn.f32x2 %0, %1, %2, %3;" : "=l"(d) : "l"(a), "l"(b), "l"(d));
}
__device__ __forceinline__ unsigned long long pack2(float x, float y) {
    unsigned long long r;
    asm("mov.b64 %0, {%1, %2};" : "=l"(r) : "f"(x), "f"(y));
    return r;
}
__device__ __forceinline__ void unpack2(unsigned long long v, float& a, float& b) {
    asm("mov.b64 {%0, %1}, %2;" : "=f"(a), "=f"(b) : "l"(v));
}
__device__ __forceinline__ float sum2(unsigned long long v) {
    float a, b; unpack2(v, a, b); return a + b;
}

// ======================= init: zero flags each launch ========================
__global__ void init_flags_kernel() {
    g_flag[threadIdx.x * 32] = 0u;
}

// ======================= Phase 1: x_proj GEMM (unchanged) ====================
#define P1T  256
#define PBM  128
#define PBN  128
#define PBK  16
#define PPAD 132

__global__ __launch_bounds__(P1T, 2) void xproj_kernel(
    const float* __restrict__ x, const float* __restrict__ W_ih,
    const float* __restrict__ b_ih, const float* __restrict__ b_hh)
{
    __shared__ float As[PBK * PPAD];
    __shared__ float Bs[PBK * PPAD];

    const int tid = threadIdx.x;
    const int tx  = tid & 15;
    const int ty  = tid >> 4;
    const long m0 = (long)blockIdx.y * PBM;
    const int  n0 = blockIdx.x * PBN;
    const int  lm = tid >> 1;
    const int  lh = tid & 1;

    unsigned long long acc[8][4];
#pragma unroll
    for (int i = 0; i < 8; i++)
#pragma unroll
        for (int j = 0; j < 4; j++) acc[i][j] = 0ull;

    for (int kt = 0; kt < 256; kt += PBK) {
        __syncthreads();
        {
            const float* xa = &x   [(m0 + lm) * 256 + kt + lh * 8];
            const float* wb = &W_ih[((long)(n0 + lm)) * 256 + kt + lh * 8];
            float4 a0 = *(const float4*)&xa[0];
            float4 a1 = *(const float4*)&xa[4];
            float4 c0 = *(const float4*)&wb[0];
            float4 c1 = *(const float4*)&wb[4];
            int kb = lh * 8;
            As[(kb + 0) * PPAD + lm] = a0.x;  As[(kb + 1) * PPAD + lm] = a0.y;
            As[(kb + 2) * PPAD + lm] = a0.z;  As[(kb + 3) * PPAD + lm] = a0.w;
            As[(kb + 4) * PPAD + lm] = a1.x;  As[(kb + 5) * PPAD + lm] = a1.y;
            As[(kb + 6) * PPAD + lm] = a1.z;  As[(kb + 7) * PPAD + lm] = a1.w;
            Bs[(kb + 0) * PPAD + lm] = c0.x;  Bs[(kb + 1) * PPAD + lm] = c0.y;
            Bs[(kb + 2) * PPAD + lm] = c0.z;  Bs[(kb + 3) * PPAD + lm] = c0.w;
            Bs[(kb + 4) * PPAD + lm] = c1.x;  Bs[(kb + 5) * PPAD + lm] = c1.y;
            Bs[(kb + 6) * PPAD + lm] = c1.z;  Bs[(kb + 7) * PPAD + lm] = c1.w;
        }
        __syncthreads();
#pragma unroll
        for (int k = 0; k < PBK; k++) {
            const float* ar = &As[k * PPAD];
            const float* br = &Bs[k * PPAD];
            float4 a0 = *(const float4*)&ar[ty * 4];
            float4 a1 = *(const float4*)&ar[64 + ty * 4];
            float4 bq0 = *(const float4*)&br[tx * 4];
            float4 bq1 = *(const float4*)&br[64 + tx * 4];
            unsigned long long bp[4];
            bp[0] = pack2(bq0.x, bq0.y);
            bp[1] = pack2(bq0.z, bq0.w);
            bp[2] = pack2(bq1.x, bq1.y);
            bp[3] = pack2(bq1.z, bq1.w);
            float am[8] = {a0.x, a0.y, a0.z, a0.w, a1.x, a1.y, a1.z, a1.w};
#pragma unroll
            for (int mi = 0; mi < 8; mi++) {
                unsigned long long ad = pack2(am[mi], am[mi]);
#pragma unroll
                for (int nj = 0; nj < 4; nj++) ffma2(acc[mi][nj], ad, bp[nj]);
            }
        }
    }

    float bias[8];
    {
        float4 i0 = *(const float4*)&b_ih[n0 + tx * 4];
        float4 i1 = *(const float4*)&b_ih[n0 + 64 + tx * 4];
        float4 h0 = *(const float4*)&b_hh[n0 + tx * 4];
        float4 h1 = *(const float4*)&b_hh[n0 + 64 + tx * 4];
        bias[0] = i0.x + h0.x; bias[1] = i0.y + h0.y;
        bias[2] = i0.z + h0.z; bias[3] = i0.w + h0.w;
        bias[4] = i1.x + h1.x; bias[5] = i1.y + h1.y;
        bias[6] = i1.z + h1.z; bias[7] = i1.w + h1.w;
    }
#pragma unroll
    for (int mi = 0; mi < 8; mi++) {
        long m = m0 + ((mi < 4) ? (ty * 4 + mi) : (64 + ty * 4 + mi - 4));
        float v0, v1, v2, v3;
        float4 o;
        unpack2(acc[mi][0], v0, v1); unpack2(acc[mi][1], v2, v3);
        o.x = v0 + bias[0]; o.y = v1 + bias[1]; o.z = v2 + bias[2]; o.w = v3 + bias[3];
        *(float4*)&g_xproj[m * G4 + n0 + tx * 4] = o;
        unpack2(acc[mi][2], v0, v1); unpack2(acc[mi][3], v2, v3);
        o.x = v0 + bias[4]; o.y = v1 + bias[5]; o.z = v2 + bias[6]; o.w = v3 + bias[7];
        *(float4*)&g_xproj[m * G4 + n0 + 64 + tx * 4] = o;
    }
}

// ======================= Phase 2: persistent LSTM recurrence =================
// 128 CTAs = 16 bg x 8 hg. W_hh in REGISTERS. Sync: per-(bg,hg) monotone flag,
// release-store by producer tid0, 8 parallel acquire-polls in warp 15.
#define GRID2 128
#define T2    512

__device__ __forceinline__ float sigm_f(float x) { return 1.f / (1.f + __expf(-x)); }
__device__ __forceinline__ float tanh_f(float x) { return 2.f / (1.f + __expf(-2.f * x)) - 1.f; }

__global__ __launch_bounds__(T2, 1)
void lstm_kernel(const float* __restrict__ W_hh, float* __restrict__ out,
                 int write_state)
{
    __shared__ __align__(16) float h2[1024];      // [k2=128][b*2+par]
    __shared__ __align__(16) float red[4 * 512];  // [kq][r][b]

    const int tid   = threadIdx.x;
    const int r     = tid & 127;               // local gate row
    const int kq    = tid >> 7;                // k quarter 0..3 (owns batch kq's xp)
    const int bg    = blockIdx.x >> 3;
    const int hg    = blockIdx.x & 7;
    const int bbase = bg * 4;
    const int jbase = hg * 32;
    const int row   = (r >> 5) * 256 + jbase + (r & 31);  // global W_hh row

    // ---- W slice into registers: 32 f32x2 pairs over k-quarter kq ----
    unsigned long long w[32];
    {
        const float2* wp = (const float2*)&W_hh[(long)row * 256 + kq * 64];
#pragma unroll
        for (int i = 0; i < 32; i++) {
            float2 f = wp[i];
            w[i] = pack2(f.x, f.y);
        }
    }

    unsigned* const my_flag = &g_flag[(bg * 8 + hg) * 32];

    // thread (r,kq) owns x_proj(batch bbase+kq, row)
    const float* xpp = &g_xproj[((long)(bbase + kq) * SS) * G4 + row];
    float xp = __ldcg(xpp);

    float c_reg = 0.f, h_last = 0.f;

    for (int t = 0; t < SS; t++) {
        const int p = t & 1;

        // ---- stage h(t-1) into smem ----
        if (t == 0) {
            *(float2*)&h2[tid * 2] = make_float2(0.f, 0.f);
        } else {
            float2 hv = __ldcg((const float2*)&g_h[p][bg * 1024 + tid * 2]);
            *(float2*)&h2[tid * 2] = hv;
        }
        __syncthreads();                                   // sync1

        // ---- k-loop: W regs x h smem (broadcast), packed over parity ----
        unsigned long long a0 = 0ull, a1 = 0ull, a2 = 0ull, a3 = 0ull;
        const float* hb = &h2[kq * 256];
#pragma unroll
        for (int k2 = 0; k2 < 32; k2++) {
            ulonglong2 lo = *(const ulonglong2*)(hb + k2 * 8);      // b0,b1
            ulonglong2 hi = *(const ulonglong2*)(hb + k2 * 8 + 4);  // b2,b3
            ffma2(a0, w[k2], lo.x);
            ffma2(a1, w[k2], lo.y);
            ffma2(a2, w[k2], hi.x);
            ffma2(a3, w[k2], hi.y);
        }
        float4 part = make_float4(sum2(a0), sum2(a1), sum2(a2), sum2(a3));
        ((float*)&part)[kq] += xp;                         // fold x_proj
        *(float4*)&red[kq * 512 + r * 4] = part;
        __syncthreads();                                   // sync2

        // ---- gather + elementwise: thread (b = tid>>5, j = tid&31) ----
        float hn = 0.f;
        if (tid < 128) {
            const int b = tid >> 5, j = tid & 31;
            float g[4];
#pragma unroll
            for (int gi = 0; gi < 4; gi++) {
                const int lr = gi * 32 + j;
                g[gi] = (red[0 * 512 + lr * 4 + b] + red[1 * 512 + lr * 4 + b]) +
                        (red[2 * 512 + lr * 4 + b] + red[3 * 512 + lr * 4 + b]);
            }
            float iv = sigm_f(g[0]);
            float fv = sigm_f(g[1]);
            float gv = tanh_f(g[2]);
            float ov = sigm_f(g[3]);
            c_reg = fv * c_reg + iv * gv;
            hn = ov * tanh_f(c_reg);
            h_last = hn;
            const int kh = jbase + j;
            g_h[p ^ 1][bg * 1024 + (kh >> 1) * 8 + b * 2 + (kh & 1)] = hn;
        }
        __syncthreads();                                   // sync3: h stores done

        // ---- publish: release-store own flag (no fence, no atomic) ----
        if (tid == 0 && t + 1 < SS) {
            unsigned v = (unsigned)(t + 1);
            asm volatile("st.release.gpu.global.u32 [%0], %1;"
                         :: "l"(my_flag), "r"(v) : "memory");
        }

        // ---- overlap: out store + xp prefetch while warp 15 polls ----
        if (tid < 128) {
            const int b = tid >> 5, j = tid & 31;
            out[(((long)(bbase + b)) * SS + t) * HH + jbase + j] = hn;
        }
        if (t + 1 < SS) xp = __ldcg(xpp + (long)(t + 1) * G4);

        // ---- 8 parallel acquire-polls on peer flags (warp 15) ----
        if (t + 1 < SS && tid >= T2 - 8) {
            const int peer = tid - (T2 - 8);
            const unsigned* fp = &g_flag[(bg * 8 + peer) * 32];
            unsigned v;
            do {
                asm volatile("ld.acquire.gpu.global.u32 %0, [%1];"
                             : "=r"(v) : "l"(fp) : "memory");
            } while (v < (unsigned)(t + 1));
        }
        __syncthreads();                                   // sync4: barrier done
    }

    if (write_state && tid < 128) {
        const int b = tid >> 5, j = tid & 31;
        const long hoff = (long)BB * SS * HH;
        out[hoff +           (bbase + b) * HH + jbase + j] = h_last;
        out[hoff + BB * HH + (bbase + b) * HH + jbase + j] = c_reg;
    }
}

// ============================= launch ========================================
extern "C" void kernel_launch(void* const* d_in, const int* in_sizes, int n_in,
                              void* d_out, int out_size)
{
    const float* x    = (const float*)d_in[0];
    const float* W_ih = (const float*)d_in[1];
    const float* W_hh = (const float*)d_in[2];
    const float* b_ih = (const float*)d_in[3];
    const float* b_hh = (const float*)d_in[4];
    float* out = (float*)d_out;

    init_flags_kernel<<<1, 128>>>();

    dim3 g1(G4 / PBN, MTOT / PBM);   // (8, 1024)
    xproj_kernel<<<g1, P1T>>>(x, W_ih, b_ih, b_hh);

    const long full = (long)BB * SS * HH + 2L * BB * HH;
    int write_state = ((long)out_size >= full) ? 1 : 0;
    lstm_kernel<<<GRID2, T2>>>(W_hh, out, write_state);
}

// round 9
// speedup vs baseline: 1.5263x; 1.5263x over previous
#include <cuda_runtime.h>
#include <cstdint>

#define BB   64
#define SS   2048
#define HH   256
#define G4   1024
#define MTOT (BB*SS)

// ---------------- scratch (device globals) -----------------------------------
__device__ float    g_xproj[(size_t)MTOT * G4];   // [B*S, 4H] (512 MB)
__device__ float    g_h[2][16 * 1024];            // [parity][bg][k2*8 + b*2 + par]
__device__ unsigned g_flag[128 * 32];             // [(bg*8+hg)*32], 128B apart

// ---------------- f32x2 packed helpers (sm_103a) -----------------------------
__device__ __forceinline__ void ffma2(unsigned long long& d,
                                      unsigned long long a, unsigned long long b) {
    asm("fma.rn.f32x2 %0, %1, %2, %3;" : "=l"(d) : "l"(a), "l"(b), "l"(d));
}
__device__ __forceinline__ unsigned long long pack2(float x, float y) {
    unsigned long long r;
    asm("mov.b64 %0, {%1, %2};" : "=l"(r) : "f"(x), "f"(y));
    return r;
}
__device__ __forceinline__ void unpack2(unsigned long long v, float& a, float& b) {
    asm("mov.b64 {%0, %1}, %2;" : "=f"(a), "=f"(b) : "l"(v));
}
__device__ __forceinline__ float sum2(unsigned long long v) {
    float a, b; unpack2(v, a, b); return a + b;
}
__device__ __forceinline__ void fence_ar_gpu() {
    asm volatile("fence.acq_rel.gpu;" ::: "memory");
}

// ======================= init: zero flags each launch ========================
__global__ void init_flags_kernel() {
    g_flag[threadIdx.x * 32] = 0u;
}

// ======================= Phase 1: x_proj GEMM (unchanged) ====================
#define P1T  256
#define PBM  128
#define PBN  128
#define PBK  16
#define PPAD 132

__global__ __launch_bounds__(P1T, 2) void xproj_kernel(
    const float* __restrict__ x, const float* __restrict__ W_ih,
    const float* __restrict__ b_ih, const float* __restrict__ b_hh)
{
    __shared__ float As[PBK * PPAD];
    __shared__ float Bs[PBK * PPAD];

    const int tid = threadIdx.x;
    const int tx  = tid & 15;
    const int ty  = tid >> 4;
    const long m0 = (long)blockIdx.y * PBM;
    const int  n0 = blockIdx.x * PBN;
    const int  lm = tid >> 1;
    const int  lh = tid & 1;

    unsigned long long acc[8][4];
#pragma unroll
    for (int i = 0; i < 8; i++)
#pragma unroll
        for (int j = 0; j < 4; j++) acc[i][j] = 0ull;

    for (int kt = 0; kt < 256; kt += PBK) {
        __syncthreads();
        {
            const float* xa = &x   [(m0 + lm) * 256 + kt + lh * 8];
            const float* wb = &W_ih[((long)(n0 + lm)) * 256 + kt + lh * 8];
            float4 a0 = *(const float4*)&xa[0];
            float4 a1 = *(const float4*)&xa[4];
            float4 c0 = *(const float4*)&wb[0];
            float4 c1 = *(const float4*)&wb[4];
            int kb = lh * 8;
            As[(kb + 0) * PPAD + lm] = a0.x;  As[(kb + 1) * PPAD + lm] = a0.y;
            As[(kb + 2) * PPAD + lm] = a0.z;  As[(kb + 3) * PPAD + lm] = a0.w;
            As[(kb + 4) * PPAD + lm] = a1.x;  As[(kb + 5) * PPAD + lm] = a1.y;
            As[(kb + 6) * PPAD + lm] = a1.z;  As[(kb + 7) * PPAD + lm] = a1.w;
            Bs[(kb + 0) * PPAD + lm] = c0.x;  Bs[(kb + 1) * PPAD + lm] = c0.y;
            Bs[(kb + 2) * PPAD + lm] = c0.z;  Bs[(kb + 3) * PPAD + lm] = c0.w;
            Bs[(kb + 4) * PPAD + lm] = c1.x;  Bs[(kb + 5) * PPAD + lm] = c1.y;
            Bs[(kb + 6) * PPAD + lm] = c1.z;  Bs[(kb + 7) * PPAD + lm] = c1.w;
        }
        __syncthreads();
#pragma unroll
        for (int k = 0; k < PBK; k++) {
            const float* ar = &As[k * PPAD];
            const float* br = &Bs[k * PPAD];
            float4 a0 = *(const float4*)&ar[ty * 4];
            float4 a1 = *(const float4*)&ar[64 + ty * 4];
            float4 bq0 = *(const float4*)&br[tx * 4];
            float4 bq1 = *(const float4*)&br[64 + tx * 4];
            unsigned long long bp[4];
            bp[0] = pack2(bq0.x, bq0.y);
            bp[1] = pack2(bq0.z, bq0.w);
            bp[2] = pack2(bq1.x, bq1.y);
            bp[3] = pack2(bq1.z, bq1.w);
            float am[8] = {a0.x, a0.y, a0.z, a0.w, a1.x, a1.y, a1.z, a1.w};
#pragma unroll
            for (int mi = 0; mi < 8; mi++) {
                unsigned long long ad = pack2(am[mi], am[mi]);
#pragma unroll
                for (int nj = 0; nj < 4; nj++) ffma2(acc[mi][nj], ad, bp[nj]);
            }
        }
    }

    float bias[8];
    {
        float4 i0 = *(const float4*)&b_ih[n0 + tx * 4];
        float4 i1 = *(const float4*)&b_ih[n0 + 64 + tx * 4];
        float4 h0 = *(const float4*)&b_hh[n0 + tx * 4];
        float4 h1 = *(const float4*)&b_hh[n0 + 64 + tx * 4];
        bias[0] = i0.x + h0.x; bias[1] = i0.y + h0.y;
        bias[2] = i0.z + h0.z; bias[3] = i0.w + h0.w;
        bias[4] = i1.x + h1.x; bias[5] = i1.y + h1.y;
        bias[6] = i1.z + h1.z; bias[7] = i1.w + h1.w;
    }
#pragma unroll
    for (int mi = 0; mi < 8; mi++) {
        long m = m0 + ((mi < 4) ? (ty * 4 + mi) : (64 + ty * 4 + mi - 4));
        float v0, v1, v2, v3;
        float4 o;
        unpack2(acc[mi][0], v0, v1); unpack2(acc[mi][1], v2, v3);
        o.x = v0 + bias[0]; o.y = v1 + bias[1]; o.z = v2 + bias[2]; o.w = v3 + bias[3];
        *(float4*)&g_xproj[m * G4 + n0 + tx * 4] = o;
        unpack2(acc[mi][2], v0, v1); unpack2(acc[mi][3], v2, v3);
        o.x = v0 + bias[4]; o.y = v1 + bias[5]; o.z = v2 + bias[6]; o.w = v3 + bias[7];
        *(float4*)&g_xproj[m * G4 + n0 + 64 + tx * 4] = o;
    }
}

// ======================= Phase 2: persistent LSTM recurrence =================
// 128 CTAs = 16 bg x 8 hg. W_hh in REGISTERS. Per-(bg,hg) monotone flag,
// published with fence+atomicAdd (R7 primitives). 8 consumer warps each poll
// one peer's flag (volatile ld) and immediately pull its 512B h chunk into
// smem -> h staging overlaps the straggler wait; 3 bar.syncs/step.
#define GRID2 128
#define T2    512

__device__ __forceinline__ float sigm_f(float x) { return 1.f / (1.f + __expf(-x)); }
__device__ __forceinline__ float tanh_f(float x) { return 2.f / (1.f + __expf(-2.f * x)) - 1.f; }

__global__ __launch_bounds__(T2, 1)
void lstm_kernel(const float* __restrict__ W_hh, float* __restrict__ out,
                 int write_state)
{
    __shared__ __align__(16) float h2[2][1024];   // [buf][k2=128][b*2+par]
    __shared__ __align__(16) float red[4 * 512];  // [kq][r][b]

    const int tid   = threadIdx.x;
    const int r     = tid & 127;               // local gate row
    const int kq    = tid >> 7;                // k quarter 0..3 (owns batch kq's xp)
    const int lane  = tid & 31;
    const int wid   = tid >> 5;                // warp 0..15
    const int bg    = blockIdx.x >> 3;
    const int hg    = blockIdx.x & 7;
    const int bbase = bg * 4;
    const int jbase = hg * 32;
    const int row   = (r >> 5) * 256 + jbase + (r & 31);  // global W_hh row

    // ---- W slice into registers: 32 f32x2 pairs over k-quarter kq ----
    unsigned long long w[32];
    {
        const float2* wp = (const float2*)&W_hh[(long)row * 256 + kq * 64];
#pragma unroll
        for (int i = 0; i < 32; i++) {
            float2 f = wp[i];
            w[i] = pack2(f.x, f.y);
        }
    }

    unsigned* const my_flag = &g_flag[(bg * 8 + hg) * 32];

    // thread (r,kq) owns x_proj(batch bbase+kq, row)
    const float* xpp = &g_xproj[((long)(bbase + kq) * SS) * G4 + row];
    float xp = __ldcg(xpp);

    // h(-1) = 0 in buffer 0
    *(float2*)&h2[0][tid * 2] = make_float2(0.f, 0.f);
    __syncthreads();

    float c_reg = 0.f, h_last = 0.f;

    for (int t = 0; t < SS; t++) {
        const int p = t & 1;

        // ---- k-loop: W regs x h2[p] smem (warp-broadcast), packed parity ----
        unsigned long long a0 = 0ull, a1 = 0ull, a2 = 0ull, a3 = 0ull;
        const float* hb = &h2[p][kq * 256];
#pragma unroll
        for (int k2 = 0; k2 < 32; k2++) {
            ulonglong2 lo = *(const ulonglong2*)(hb + k2 * 8);      // b0,b1
            ulonglong2 hi = *(const ulonglong2*)(hb + k2 * 8 + 4);  // b2,b3
            ffma2(a0, w[k2], lo.x);
            ffma2(a1, w[k2], lo.y);
            ffma2(a2, w[k2], hi.x);
            ffma2(a3, w[k2], hi.y);
        }
        float4 part = make_float4(sum2(a0), sum2(a1), sum2(a2), sum2(a3));
        ((float*)&part)[kq] += xp;                         // fold x_proj
        *(float4*)&red[kq * 512 + r * 4] = part;
        __syncthreads();                                   // sync A

        // ---- gather + elementwise: thread (b = tid>>5, j = tid&31) ----
        float hn = 0.f;
        if (tid < 128) {
            const int b = tid >> 5, j = tid & 31;
            float g[4];
#pragma unroll
            for (int gi = 0; gi < 4; gi++) {
                const int lr = gi * 32 + j;
                g[gi] = (red[0 * 512 + lr * 4 + b] + red[1 * 512 + lr * 4 + b]) +
                        (red[2 * 512 + lr * 4 + b] + red[3 * 512 + lr * 4 + b]);
            }
            float iv = sigm_f(g[0]);
            float fv = sigm_f(g[1]);
            float gv = tanh_f(g[2]);
            float ov = sigm_f(g[3]);
            c_reg = fv * c_reg + iv * gv;
            hn = ov * tanh_f(c_reg);
            h_last = hn;
            const int kh = jbase + j;
            g_h[p ^ 1][bg * 1024 + (kh >> 1) * 8 + b * 2 + (kh & 1)] = hn;
            out[(((long)(bbase + b)) * SS + t) * HH + jbase + j] = hn;
        }
        __syncthreads();                                   // sync B: h stores done

        if (t + 1 < SS) {
            // prefetch next xp (issue early; consumed next iteration)
            float xp_n = __ldcg(xpp + (long)(t + 1) * G4);

            // ---- publish own flag: fence + atomic (R7 fast path) ----
            if (tid == 0) {
                fence_ar_gpu();
                atomicAdd(my_flag, 1u);
            }

            // ---- consumer warps 8..15: poll peer flag, pull its h chunk ----
            if (wid >= 8) {
                const int peer = wid - 8;
                if (lane == 0) {
                    const unsigned* fp = &g_flag[(bg * 8 + peer) * 32];
                    while (*((volatile unsigned*)fp) < (unsigned)(t + 1)) { }
                }
                __syncwarp();
                float4 hv = __ldcg((const float4*)
                    &g_h[p ^ 1][bg * 1024 + peer * 128 + lane * 4]);
                *(float4*)&h2[p ^ 1][peer * 128 + lane * 4] = hv;
            }
            xp = xp_n;
        }
        __syncthreads();                                   // sync C
    }

    if (write_state && tid < 128) {
        const int b = tid >> 5, j = tid & 31;
        const long hoff = (long)BB * SS * HH;
        out[hoff +           (bbase + b) * HH + jbase + j] = h_last;
        out[hoff + BB * HH + (bbase + b) * HH + jbase + j] = c_reg;
    }
}

// ============================= launch ========================================
extern "C" void kernel_launch(void* const* d_in, const int* in_sizes, int n_in,
                              void* d_out, int out_size)
{
    const float* x    = (const float*)d_in[0];
    const float* W_ih = (const float*)d_in[1];
    const float* W_hh = (const float*)d_in[2];
    const float* b_ih = (const float*)d_in[3];
    const float* b_hh = (const float*)d_in[4];
    float* out = (float*)d_out;

    init_flags_kernel<<<1, 128>>>();

    dim3 g1(G4 / PBN, MTOT / PBM);   // (8, 1024)
    xproj_kernel<<<g1, P1T>>>(x, W_ih, b_ih, b_hh);

    const long full = (long)BB * SS * HH + 2L * BB * HH;
    int write_state = ((long)out_size >= full) ? 1 : 0;
    lstm_kernel<<<GRID2, T2>>>(W_hh, out, write_state);
}